// round 12
// baseline (speedup 1.0000x reference)
#include <cuda_runtime.h>
#include <cuda_fp16.h>
#include <cstdint>

#define NN 256
#define NT 2048
#define NF 128

__device__ __half g_adj16[NN * NN];   // rownorm(adj+I), fp16, [m][k]

__device__ __forceinline__ uint32_t smem_u32(const void* p) {
    uint32_t a;
    asm("{ .reg .u64 t; cvta.to.shared.u64 t, %1; cvt.u32.u64 %0, t; }" : "=r"(a) : "l"(p));
    return a;
}
__device__ __forceinline__ uint32_t packh2(float x, float y) {
    __half2 h = __floats2half2_rn(x, y);
    return *reinterpret_cast<uint32_t*>(&h);
}
template <int N> __device__ __forceinline__ void cp_wait() {
    asm volatile("cp.async.wait_group %0;" :: "n"(N) : "memory");
}
#define CP_ASYNC16(dst, src) \
    asm volatile("cp.async.cg.shared.global [%0], [%1], 16;" :: "r"(dst), "l"(src) : "memory")
#define CP_COMMIT() asm volatile("cp.async.commit_group;" ::: "memory")

// ---------------------------------------------------------------------------
__global__ void prep_kernel(const float* __restrict__ adj) {
    __shared__ float red[256];
    int m = blockIdx.x, j = threadIdx.x;
    float v = adj[m * NN + j] + (j == m ? 1.0f : 0.0f);
    red[j] = v;
    __syncthreads();
#pragma unroll
    for (int off = 128; off > 0; off >>= 1) {
        if (j < off) red[j] += red[j + off];
        __syncthreads();
    }
    g_adj16[m * NN + j] = __float2half_rn(v / red[0]);
}

// ---------------------------------------------------------------------------
// Fused GCN: one CTA per t. 256 threads = 8 warps (4m x 2n), warp tile 64x64.
// Phase 1: reg-staged double buffer (fp32->fp16 cvt). Phase 2: cp.async
// 3-stage ring (no register transients, no STS-on-LDG dependency).
//
// smem (156 KB dynamic):
//   SW  [0,      32768): W fp16, 128 rows x 256B, XOR swizzle
//   SXW [32768,  98304): xw slab fp16, 256 rows x 256B, XOR swizzle
//   STG [98304, 159744): A staging, 3 stages x (256 rows x 80B)
//        (phase 1 uses stages 0/1; phase 2 cycles all 3)
// ---------------------------------------------------------------------------
#define SW_OFF   0
#define SXW_OFF  32768
#define STG_OFF  98304
#define ASTAGE   20480
#define SMEM_TOT 159744

__global__ void __launch_bounds__(256, 1)
fused_gcn(const float* __restrict__ X, const float* __restrict__ W,
          float* __restrict__ out, const float* __restrict__ bias)
{
    extern __shared__ __align__(128) char smem[];
    const uint32_t base = smem_u32(smem);
    const uint32_t SW  = base + SW_OFF;
    const uint32_t SXW = base + SXW_OFF;
    const uint32_t STG = base + STG_OFF;

    const int t    = blockIdx.x;
    const int tid  = threadIdx.x;
    const int warp = tid >> 5;
    const int lane = tid & 31;
    const int lr   = lane & 15, lh = lane >> 4;
    const int grp  = lane >> 2, tg = lane & 3;
    const int warp_m = (warp & 3) * 64;
    const int warp_n = (warp >> 2) * 64;

    float acc[4][8][4];     // 128 regs
    float4 xr[4][2];        // phase-1 staging transients only

    auto zero_acc = [&] {
#pragma unroll
        for (int i = 0; i < 4; i++)
#pragma unroll
            for (int j = 0; j < 8; j++)
#pragma unroll
                for (int r = 0; r < 4; r++) acc[i][j][r] = 0.0f;
    };
    auto sts16 = [](uint32_t addr, uint4 v) {
        asm volatile("st.shared.v4.b32 [%0], {%1,%2,%3,%4};"
                     :: "r"(addr), "r"(v.x), "r"(v.y), "r"(v.z), "r"(v.w) : "memory");
    };

    // ---- phase-1 producers (reg path, fp32 -> fp16) ----
    auto loadX = [&](int c) {
#pragma unroll
        for (int i = 0; i < 4; i++) {
            int u = tid + i * 256;
            int row = u >> 2, seg = u & 3;
            const float4* src = (const float4*)(X + ((size_t)row * NT + t) * NF + c * 32 + seg * 8);
            xr[i][0] = src[0];
            xr[i][1] = src[1];
        }
    };
    auto stsX = [&](int s) {
#pragma unroll
        for (int i = 0; i < 4; i++) {
            int u = tid + i * 256;
            int row = u >> 2, seg = u & 3;
            uint4 v;
            v.x = packh2(xr[i][0].x, xr[i][0].y); v.y = packh2(xr[i][0].z, xr[i][0].w);
            v.z = packh2(xr[i][1].x, xr[i][1].y); v.w = packh2(xr[i][1].z, xr[i][1].w);
            sts16(STG + s * ASTAGE + row * 80 + seg * 16, v);
        }
    };

    // ---- phase-2 producer: cp.async one BK32 adj chunk into stage s ----
    auto acp = [&](int c, int s) {
        const uint32_t as = STG + s * ASTAGE;
#pragma unroll
        for (int i = 0; i < 4; i++) {
            int u = tid + i * 256;
            int row = u >> 2, seg = u & 3;
            CP_ASYNC16(as + row * 80 + seg * 16,
                       g_adj16 + row * NN + c * 32 + seg * 8);
        }
        CP_COMMIT();
    };

    // one BK32 chunk of mma: A from staging stage s, B from Bbase (XOR rows)
    auto mma_stage = [&](int c, int s, uint32_t Bbase) {
        const uint32_t ab = STG + s * ASTAGE;
#pragma unroll
        for (int kk = 0; kk < 2; kk++) {
            const int ke = kk * 16;
            uint32_t a[4][4];
#pragma unroll
            for (int fm = 0; fm < 4; fm++) {
                uint32_t ad = ab + (warp_m + fm * 16 + lr) * 80 + lh * 16 + ke * 2;
                asm volatile("ldmatrix.sync.aligned.m8n8.x4.shared.b16 {%0,%1,%2,%3}, [%4];"
                             : "=r"(a[fm][0]), "=r"(a[fm][1]), "=r"(a[fm][2]), "=r"(a[fm][3])
                             : "r"(ad));
            }
            uint32_t b[4][4];
#pragma unroll
            for (int np = 0; np < 4; np++) {
                int krw = c * 32 + ke + lr;
                uint32_t bn = (uint32_t)(warp_n + np * 16 + lh * 8) * 2;
                uint32_t bd = Bbase + krw * 256 + (bn ^ ((krw & 7) << 4));
                asm volatile("ldmatrix.sync.aligned.m8n8.x4.trans.shared.b16 {%0,%1,%2,%3}, [%4];"
                             : "=r"(b[np][0]), "=r"(b[np][1]), "=r"(b[np][2]), "=r"(b[np][3])
                             : "r"(bd));
            }
#pragma unroll
            for (int fm = 0; fm < 4; fm++)
#pragma unroll
                for (int fn = 0; fn < 8; fn++) {
                    const int np = fn >> 1, pr = fn & 1;
                    asm volatile(
                        "mma.sync.aligned.m16n8k16.row.col.f32.f16.f16.f32 "
                        "{%0,%1,%2,%3}, {%4,%5,%6,%7}, {%8,%9}, {%0,%1,%2,%3};"
                        : "+f"(acc[fm][fn][0]), "+f"(acc[fm][fn][1]),
                          "+f"(acc[fm][fn][2]), "+f"(acc[fm][fn][3])
                        : "r"(a[fm][0]), "r"(a[fm][1]), "r"(a[fm][2]), "r"(a[fm][3]),
                          "r"(b[np][pr * 2]), "r"(b[np][pr * 2 + 1]));
                }
        }
    };

    // ---- prologue: W -> SW (swizzled), X chunk 0 -> stage 0 ----
#pragma unroll
    for (int p = 0; p < 8; p++) {
        int u = tid + p * 256;
        int row = u >> 4, seg = u & 15;
        const float4* src = (const float4*)(W + row * NF + seg * 8);
        float4 v0 = src[0], v1 = src[1];
        uint4 w;
        w.x = packh2(v0.x, v0.y); w.y = packh2(v0.z, v0.w);
        w.z = packh2(v1.x, v1.y); w.w = packh2(v1.z, v1.w);
        sts16(SW + row * 256 + ((seg * 16) ^ ((row & 7) << 4)), w);
    }
    loadX(0);
    stsX(0);
    zero_acc();
    __syncthreads();

    // ---- phase 1: xw = X_t @ W (K=128, 4 chunks, double-buffered) ----
#pragma unroll
    for (int c = 0; c < 4; c++) {
        const int s = c & 1;
        if (c < 3) loadX(c + 1);
        mma_stage(c, s, SW);
        if (c < 3) { stsX(s ^ 1); __syncthreads(); }
    }
    __syncthreads();               // seal all phase-1 staging reads

    // ---- kick off adj chunks 0,1 (fly during the epilogue) ----
    acp(0, 0);
    acp(1, 1);

    // phase-1 epilogue: acc -> SXW (fp16, XOR swizzle)
#pragma unroll
    for (int fm = 0; fm < 4; fm++) {
        const int r0 = warp_m + fm * 16 + grp;
#pragma unroll
        for (int fn = 0; fn < 8; fn++) {
            const int cb = (warp_n + fn * 8 + tg * 2) * 2;
            uint32_t h0 = packh2(acc[fm][fn][0], acc[fm][fn][1]);
            uint32_t h1 = packh2(acc[fm][fn][2], acc[fm][fn][3]);
            asm volatile("st.shared.b32 [%0], %1;"
                         :: "r"(SXW + r0 * 256 + (cb ^ ((r0 & 7) << 4))), "r"(h0) : "memory");
            asm volatile("st.shared.b32 [%0], %1;"
                         :: "r"(SXW + (r0 + 8) * 256 + (cb ^ (((r0 + 8) & 7) << 4))), "r"(h1) : "memory");
        }
    }
    zero_acc();
    cp_wait<1>();                  // adj chunk 0 resident
    __syncthreads();

    // ---- phase 2: out = adj_hat @ xw + bias (K=256, 8 chunks, 3-stage) ----
#pragma unroll
    for (int c = 0; c < 8; c++) {
        const int s = c % 3;
        mma_stage(c, s, SXW);
        if (c + 2 < 8) acp(c + 2, (c + 2) % 3);   // writes stage (c-1)%3: sealed
        if (c < 7) {
            if (c + 2 < 8) cp_wait<1>(); else cp_wait<0>();
            __syncthreads();
        }
    }

    // phase-2 epilogue
#pragma unroll
    for (int fm = 0; fm < 4; fm++) {
        const int r0 = warp_m + fm * 16 + grp;
#pragma unroll
        for (int fn = 0; fn < 8; fn++) {
            const int col = warp_n + fn * 8 + tg * 2;
            float2 b2 = *(const float2*)(bias + col);
            float2 v0 = { acc[fm][fn][0] + b2.x, acc[fm][fn][1] + b2.y };
            float2 v1 = { acc[fm][fn][2] + b2.x, acc[fm][fn][3] + b2.y };
            *(float2*)(out + ((size_t)r0 * NT + t) * NF + col)       = v0;
            *(float2*)(out + ((size_t)(r0 + 8) * NT + t) * NF + col) = v1;
        }
    }
}

// ---------------------------------------------------------------------------
extern "C" void kernel_launch(void* const* d_in, const int* in_sizes, int n_in,
                              void* d_out, int out_size) {
    (void)in_sizes; (void)n_in; (void)out_size;
    const float* node_feats = (const float*)d_in[0];   // [256,2048,128]
    const float* adj        = (const float*)d_in[1];   // [256,256]
    const float* weight     = (const float*)d_in[2];   // [128,128]
    const float* bias       = (const float*)d_in[3];   // [128]
    float* out = (float*)d_out;

    cudaFuncSetAttribute(fused_gcn, cudaFuncAttributeMaxDynamicSharedMemorySize, SMEM_TOT);

    prep_kernel<<<NN, 256>>>(adj);
    fused_gcn<<<NT, 256, SMEM_TOT>>>(node_feats, weight, out, bias);
}